// round 16
// baseline (speedup 1.0000x reference)
#include <cuda_runtime.h>

#define LOG2E 1.4426950408889634f
#define N_EN  20000
#define M_MEN 256

// Block: 256 threads = 8 warps. Warp = 4 entities x 8 chunk-slots.
//   lane = n_sub*8 + c  (n_sub in 0..3, c in 0..7)
// Thread: entity chunk (n, c) in registers; loops 32 mentions; mention chunk
// from padded smem (8 distinct addrs/warp, conflict-free).
// LINEAR-SPACE variant: thread computes the raw chunk product (no lg2);
// butterfly reduce multiplies across the 8 chunk lanes; output is
// P * rcp(G_self) -- no per-chunk LG2, no final EX2.
// Split per chunk: 4 dims MUFU path, 4 dims scalar-poly path.

__device__ __forceinline__ float ex2f(float x){float r;asm("ex2.approx.ftz.f32 %0,%1;":"=f"(r):"f"(x));return r;}
__device__ __forceinline__ float lg2f(float x){float r;asm("lg2.approx.ftz.f32 %0,%1;":"=f"(r):"f"(x));return r;}
__device__ __forceinline__ float rcpf(float x){float r;asm("rcp.approx.ftz.f32 %0,%1;":"=f"(r):"f"(x));return r;}

// R(t) = Q(t)/t, Q ~= log2(1+t) on [0,1] (deg-6 Chebyshev closed form,
// z=3-2*sqrt2; b0 dropped -- t-independent bias cancels through the G ratio).
// R in [0.693,1.443] > 0 -> v > 0, chunk products positive.
__device__ __forceinline__ float r_poly(float t){
    float q = fmaf(-0.02512518f, t, 0.1193046f);
    q = fmaf(q, t, -0.2746312f);
    q = fmaf(q, t,  0.4555314f);
    q = fmaf(q, t, -0.7175598f);
    q = fmaf(q, t,  1.4424753f);
    return q;
}

// One 8-dim chunk: prod_d log2(1+2^{y_d}), y = min(mZ,eZ)-max(mz,ez).
// ml: 16 floats (lo[0..7], hi[8..15]); ez/eZ: entity registers.
// dims 0-3: MUFU path  v = lg2(1+ex2(y))
// dims 4-7: poly path  v = relu(y) + t*R(t), t = 2^-|y|
__device__ __forceinline__ float chunk_prod(const float* ml,
                                            const float* ez, const float* eZ){
    float va[4];
#pragma unroll
    for (int d = 0; d < 4; ++d){
        float y = fminf(ml[8+d], eZ[d]) - fmaxf(ml[d], ez[d]);
        va[d] = lg2f(1.f + ex2f(y));
    }
    float vb[4];
#pragma unroll
    for (int d = 4; d < 8; ++d){
        float y = fminf(ml[8+d], eZ[d]) - fmaxf(ml[d], ez[d]);
        float t = ex2f(-fabsf(y));
        vb[d-4] = fmaf(t, r_poly(t), fmaxf(y, 0.f));
    }
    float t1 = va[0] * va[1];
    float t2 = va[2] * va[3];
    float t3 = vb[0] * vb[1];
    float t4 = vb[2] * vb[3];
    return (t1 * t2) * (t3 * t4);
}

// Padded mention smem: per mention 8 chunks x 20 floats (16 data + 4 pad);
// chunk stride 80B -> 8 c-addresses in disjoint bank groups.
#define MSTR 160

__global__ __launch_bounds__(256, 4) void ivr_kernel(const float* __restrict__ men,
                                                     const float* __restrict__ en,
                                                     float* __restrict__ out){
    __shared__ float s_men[32 * MSTR];
    __shared__ float s_gmp[256];
    __shared__ float s_w8[32];     // rcp(self-volume product) per mention

    const int tid  = threadIdx.x;
    const int lane = tid & 31;
    const int wid  = tid >> 5;
    const int c    = lane & 7;
    const int nsub = lane >> 3;
    const int m0   = blockIdx.y * 32;

    for (int idx = tid; idx < 32 * 128; idx += 256){
        int m = idx >> 7, d = idx & 127;
        int cc = (d & 63) >> 3, k = d & 7, off = (d >= 64) ? 8 : 0;
        s_men[m * MSTR + cc * 20 + off + k] = men[(m0 + m) * 128 + d] * LOG2E;
    }
    __syncthreads();

    // per-mention self volume (identical value path -> approx error cancels
    // through the final ratio)
    {
        int mi = tid >> 3, ci = tid & 7;
        const float* p = s_men + mi * MSTR + ci * 20;
        float ml[16];
#pragma unroll
        for (int k = 0; k < 16; ++k) ml[k] = p[k];
        s_gmp[tid] = chunk_prod(ml, ml, ml + 8);
    }
    __syncthreads();
    if (tid < 32){
        float g = s_gmp[tid * 8];
#pragma unroll
        for (int i = 1; i < 8; ++i) g *= s_gmp[tid * 8 + i];
        s_w8[tid] = rcpf(g);      // G_self in 2^{+-40}: safe range
    }
    __syncthreads();

    // entity chunk -> registers (prescaled). 20000 = 625*32, no guard.
    const int n = blockIdx.x * 32 + wid * 4 + nsub;
    float ez[8], eZ[8];
    {
        const float* erow = en + (size_t)n * 128;
        float4 a0 = *(const float4*)(erow + c * 8);
        float4 a1 = *(const float4*)(erow + c * 8 + 4);
        float4 b0 = *(const float4*)(erow + 64 + c * 8);
        float4 b1 = *(const float4*)(erow + 64 + c * 8 + 4);
        ez[0]=a0.x*LOG2E; ez[1]=a0.y*LOG2E; ez[2]=a0.z*LOG2E; ez[3]=a0.w*LOG2E;
        ez[4]=a1.x*LOG2E; ez[5]=a1.y*LOG2E; ez[6]=a1.z*LOG2E; ez[7]=a1.w*LOG2E;
        eZ[0]=b0.x*LOG2E; eZ[1]=b0.y*LOG2E; eZ[2]=b0.z*LOG2E; eZ[3]=b0.w*LOG2E;
        eZ[4]=b1.x*LOG2E; eZ[5]=b1.y*LOG2E; eZ[6]=b1.z*LOG2E; eZ[7]=b1.w*LOG2E;
    }

    const float* mbase = s_men + c * 20;

#pragma unroll 8
    for (int m = 0; m < 32; ++m){
        const float* p = mbase + m * MSTR;
        float ml[16];
        {
            float4 q0 = *(const float4*)(p);
            float4 q1 = *(const float4*)(p + 4);
            float4 q2 = *(const float4*)(p + 8);
            float4 q3 = *(const float4*)(p + 12);
            ml[0]=q0.x;  ml[1]=q0.y;  ml[2]=q0.z;  ml[3]=q0.w;
            ml[4]=q1.x;  ml[5]=q1.y;  ml[6]=q1.z;  ml[7]=q1.w;
            ml[8]=q2.x;  ml[9]=q2.y;  ml[10]=q2.z; ml[11]=q2.w;
            ml[12]=q3.x; ml[13]=q3.y; ml[14]=q3.z; ml[15]=q3.w;
        }
        float v = chunk_prod(ml, ez, eZ);
        // product all-reduce across the 8 chunk lanes
        v *= __shfl_xor_sync(0xFFFFFFFFu, v, 1);
        v *= __shfl_xor_sync(0xFFFFFFFFu, v, 2);
        v *= __shfl_xor_sync(0xFFFFFFFFu, v, 4);
        if (c == 0){
            out[(size_t)(m0 + m) * N_EN + n] = v * s_w8[m];
        }
    }
}

extern "C" void kernel_launch(void* const* d_in, const int* in_sizes, int n_in,
                              void* d_out, int out_size){
    const float* men = (const float*)d_in[0];
    const float* en  = (const float*)d_in[1];
    if (n_in >= 2 && in_sizes[0] > in_sizes[1]){
        const float* t = men; men = en; en = t;
    }
    float* out = (float*)d_out;

    dim3 grid(N_EN / 32, M_MEN / 32);   // 625 x 8
    ivr_kernel<<<grid, 256>>>(men, en, out);
}

// round 17
// speedup vs baseline: 1.4919x; 1.4919x over previous
#include <cuda_runtime.h>

#define LOG2E 1.4426950408889634f
#define N_EN  20000
#define M_MEN 256

// Block: 256 threads = 8 warps. Warp = 4 entities x 8 chunk-slots.
//   lane = n_sub*8 + c  (n_sub in 0..3, c in 0..7)
// Thread: entity chunk (n, c) in registers; loops 32 mentions; mention chunk
// from padded smem (8 distinct addrs/warp, conflict-free).
// R14 skeleton (a=5 split, unroll 8, 4 CTAs/SM) + LINEAR-SPACE reduction:
// thread returns raw chunk product (no lg2), butterfly multiplies across the
// 8 chunk lanes, epilogue is v * rcp(G_self) -- no per-chunk LG2, no final EX2.

__device__ __forceinline__ float ex2f(float x){float r;asm("ex2.approx.ftz.f32 %0,%1;":"=f"(r):"f"(x));return r;}
__device__ __forceinline__ float lg2f(float x){float r;asm("lg2.approx.ftz.f32 %0,%1;":"=f"(r):"f"(x));return r;}
__device__ __forceinline__ float rcpf(float x){float r;asm("rcp.approx.ftz.f32 %0,%1;":"=f"(r):"f"(x));return r;}

// Deg-6 poly Q(t) ~= log2(1+t) on [0,1] (closed-form Chebyshev, z=3-2*sqrt2).
// Q(0)=3.84e-6 > 0 keeps chunk products positive.
__device__ __forceinline__ float q_log2_1p(float t){
    float q = fmaf(-0.02512518f, t, 0.1193046f);
    q = fmaf(q, t, -0.2746312f);
    q = fmaf(q, t,  0.4555314f);
    q = fmaf(q, t, -0.7175598f);
    q = fmaf(q, t,  1.4424753f);
    q = fmaf(q, t,  3.84e-6f);
    return q;
}

// One 8-dim chunk: prod_d log2(1+2^{y_d}), y = min(mZ,eZ)-max(mz,ez).
// ml: 16 floats (lo[0..7], hi[8..15]); ez/eZ: entity registers.
// dims 0-4: MUFU path  v = lg2(1+ex2(y))
// dims 5-7: poly path  v = relu(y) + Q(2^-|y|)
__device__ __forceinline__ float chunk_prod(const float* ml,
                                            const float* ez, const float* eZ){
    float va[5];
#pragma unroll
    for (int d = 0; d < 5; ++d){
        float y = fminf(ml[8+d], eZ[d]) - fmaxf(ml[d], ez[d]);
        va[d] = lg2f(1.f + ex2f(y));
    }
    float vb[3];
#pragma unroll
    for (int d = 5; d < 8; ++d){
        float y = fminf(ml[8+d], eZ[d]) - fmaxf(ml[d], ez[d]);
        float t = ex2f(-fabsf(y));
        vb[d-5] = fmaxf(y, 0.f) + q_log2_1p(t);
    }
    float t1 = va[0] * va[1];
    float t2 = va[2] * va[3];
    float t3 = va[4] * vb[0];
    float t4 = vb[1] * vb[2];
    return (t1 * t2) * (t3 * t4);
}

// Padded mention smem: per mention 8 chunks x 20 floats (16 data + 4 pad);
// chunk stride 80B -> 8 c-addresses in disjoint bank groups.
#define MSTR 160

__global__ __launch_bounds__(256, 4) void ivr_kernel(const float* __restrict__ men,
                                                     const float* __restrict__ en,
                                                     float* __restrict__ out){
    __shared__ float s_men[32 * MSTR];
    __shared__ float s_gmp[256];
    __shared__ float s_w8[32];   // rcp(self-volume product) per mention

    const int tid  = threadIdx.x;
    const int lane = tid & 31;
    const int wid  = tid >> 5;
    const int c    = lane & 7;
    const int nsub = lane >> 3;
    const int m0   = blockIdx.y * 32;

    for (int idx = tid; idx < 32 * 128; idx += 256){
        int m = idx >> 7, d = idx & 127;
        int cc = (d & 63) >> 3, k = d & 7, off = (d >= 64) ? 8 : 0;
        s_men[m * MSTR + cc * 20 + off + k] = men[(m0 + m) * 128 + d] * LOG2E;
    }
    __syncthreads();

    // per-mention self volume (identical value path -> approx error cancels
    // through the final ratio). G_self in 2^{+-40}: safe fp32 range.
    {
        int mi = tid >> 3, ci = tid & 7;
        const float* p = s_men + mi * MSTR + ci * 20;
        float ml[16];
#pragma unroll
        for (int k = 0; k < 16; ++k) ml[k] = p[k];
        s_gmp[tid] = chunk_prod(ml, ml, ml + 8);
    }
    __syncthreads();
    if (tid < 32){
        float g = s_gmp[tid * 8];
#pragma unroll
        for (int i = 1; i < 8; ++i) g *= s_gmp[tid * 8 + i];
        s_w8[tid] = rcpf(g);
    }
    __syncthreads();

    // entity chunk -> registers (prescaled). 20000 = 625*32, no guard.
    const int n = blockIdx.x * 32 + wid * 4 + nsub;
    float ez[8], eZ[8];
    {
        const float* erow = en + (size_t)n * 128;
        float4 a0 = *(const float4*)(erow + c * 8);
        float4 a1 = *(const float4*)(erow + c * 8 + 4);
        float4 b0 = *(const float4*)(erow + 64 + c * 8);
        float4 b1 = *(const float4*)(erow + 64 + c * 8 + 4);
        ez[0]=a0.x*LOG2E; ez[1]=a0.y*LOG2E; ez[2]=a0.z*LOG2E; ez[3]=a0.w*LOG2E;
        ez[4]=a1.x*LOG2E; ez[5]=a1.y*LOG2E; ez[6]=a1.z*LOG2E; ez[7]=a1.w*LOG2E;
        eZ[0]=b0.x*LOG2E; eZ[1]=b0.y*LOG2E; eZ[2]=b0.z*LOG2E; eZ[3]=b0.w*LOG2E;
        eZ[4]=b1.x*LOG2E; eZ[5]=b1.y*LOG2E; eZ[6]=b1.z*LOG2E; eZ[7]=b1.w*LOG2E;
    }

    const float* mbase = s_men + c * 20;

#pragma unroll 8
    for (int m = 0; m < 32; ++m){
        const float* p = mbase + m * MSTR;
        float ml[16];
        {
            float4 q0 = *(const float4*)(p);
            float4 q1 = *(const float4*)(p + 4);
            float4 q2 = *(const float4*)(p + 8);
            float4 q3 = *(const float4*)(p + 12);
            ml[0]=q0.x;  ml[1]=q0.y;  ml[2]=q0.z;  ml[3]=q0.w;
            ml[4]=q1.x;  ml[5]=q1.y;  ml[6]=q1.z;  ml[7]=q1.w;
            ml[8]=q2.x;  ml[9]=q2.y;  ml[10]=q2.z; ml[11]=q2.w;
            ml[12]=q3.x; ml[13]=q3.y; ml[14]=q3.z; ml[15]=q3.w;
        }
        float v = chunk_prod(ml, ez, eZ);
        // product all-reduce across the 8 chunk lanes
        v *= __shfl_xor_sync(0xFFFFFFFFu, v, 1);
        v *= __shfl_xor_sync(0xFFFFFFFFu, v, 2);
        v *= __shfl_xor_sync(0xFFFFFFFFu, v, 4);
        if (c == 0){
            out[(size_t)(m0 + m) * N_EN + n] = v * s_w8[m];
        }
    }
}

extern "C" void kernel_launch(void* const* d_in, const int* in_sizes, int n_in,
                              void* d_out, int out_size){
    const float* men = (const float*)d_in[0];
    const float* en  = (const float*)d_in[1];
    if (n_in >= 2 && in_sizes[0] > in_sizes[1]){
        const float* t = men; men = en; en = t;
    }
    float* out = (float*)d_out;

    dim3 grid(N_EN / 32, M_MEN / 32);   // 625 x 8
    ivr_kernel<<<grid, 256>>>(men, en, out);
}